// round 8
// baseline (speedup 1.0000x reference)
#include <cuda_runtime.h>
#include <cstdint>

#define D 128
#define TM 64
#define THREADS 256
#define AROW 132                        // floats per k-row of dup'd activation tile (128 dup + 4 pad)
#define SA_F (128 * AROW)               // one k-half, duplicated: 16896 floats
#define SW_F (256 * 128)                // full W1
#define SMEM_BYTES ((SA_F + SW_F) * 4)  // 198,656 B

#define SC_WARPS 8                      // warps per scatter CTA
#define SC_BATCH 4                      // edges per warp per iteration
#define SC_CTAS  592                    // 4 CTAs/SM

// Scratch for the scatter-add aggregate (25.6 MB). Static __device__ array per rules.
__device__ float g_agg[50000 * D];

__device__ __forceinline__ uint32_t smem_u32(const void* p) {
    uint32_t a;
    asm("{ .reg .u64 t; cvta.to.shared.u64 t, %1; cvt.u32.u64 %0, t; }"
        : "=r"(a) : "l"(p));
    return a;
}

// ---------------------------------------------------------------------------
__global__ void zero_agg_kernel(int n4) {
    int i = blockIdx.x * blockDim.x + threadIdx.x;
    if (i < n4) {
        float4 z = {0.f, 0.f, 0.f, 0.f};
        reinterpret_cast<float4*>(g_agg)[i] = z;
    }
}

// ---------------------------------------------------------------------------
// Scatter via TMA bulk-reduce: each warp stages SC_BATCH edge rows (512B each)
// in smem, then lanes 0..3 each issue ONE cp.reduce.async.bulk .add.f32 of
// 512B into g_agg[recv[e]]. The async proxy does the atomic adds at the LTS
// at bulk rate; the SM only pays LDG+STS+issue (vs 32 REDG lanes per edge).
// Double-buffered per warp; wait_group.read gates slot reuse.
__global__ __launch_bounds__(THREADS)
void scatter_tma_kernel(const float* __restrict__ edge_attr,
                        const int* __restrict__ recv, int E, int totalWarps) {
    __shared__ __align__(16) float buf[SC_WARPS][2][SC_BATCH * D];
    const int lane = threadIdx.x & 31;
    const int warp = threadIdx.x >> 5;
    const int gw   = blockIdx.x * SC_WARPS + warp;

    int iter = 0;
    for (long long e0 = (long long)gw * SC_BATCH; e0 < E;
         e0 += (long long)totalWarps * SC_BATCH, iter++) {
        const int slot = iter & 1;
        const int nb = (int)(((long long)E - e0) < SC_BATCH ? (E - e0) : SC_BATCH);

        // Before overwriting this slot, the reduce issued from it (2 iters ago)
        // must have finished READING smem.
        if (iter >= 2 && lane < SC_BATCH)
            asm volatile("cp.async.bulk.wait_group.read 1;" ::: "memory");
        __syncwarp();

        // Stage: lane carries 16B of each of the nb edge rows (MLP=4 LDGs).
        float4 v[SC_BATCH];
        #pragma unroll
        for (int j = 0; j < SC_BATCH; j++)
            if (j < nb)
                v[j] = reinterpret_cast<const float4*>(edge_attr + (e0 + j) * D)[lane];
        #pragma unroll
        for (int j = 0; j < SC_BATCH; j++)
            if (j < nb)
                reinterpret_cast<float4*>(&buf[warp][slot][j * D])[lane] = v[j];

        // Order generic-proxy STS before async-proxy bulk read.
        asm volatile("fence.proxy.async.shared::cta;" ::: "memory");
        __syncwarp();

        // Lanes 0..nb-1 each issue one 512B bulk reduce for their edge.
        if (lane < nb) {
            int r = recv[e0 + lane];
            uint32_t saddr = smem_u32(&buf[warp][slot][lane * D]);
            float* dst = g_agg + (size_t)r * D;
            asm volatile(
                "cp.reduce.async.bulk.global.shared::cta.bulk_group.add.f32 "
                "[%0], [%1], %2;"
                :: "l"(dst), "r"(saddr), "r"(512) : "memory");
            asm volatile("cp.async.bulk.commit_group;" ::: "memory");
        }
    }
    // All reduces must fully complete before the kernel ends (next kernel reads g_agg).
    if (lane < SC_BATCH)
        asm volatile("cp.async.bulk.wait_group 0;" ::: "memory");
}

// ---------------------------------------------------------------------------
// Packed-f32x2 helpers (sm_100+). Exact fp32 math, 2 FMAs per instruction.
__device__ __forceinline__ void fma2(unsigned long long& d,
                                     unsigned long long a, unsigned long long b) {
    asm("fma.rn.f32x2 %0, %1, %2, %0;" : "+l"(d) : "l"(a), "l"(b));
}
__device__ __forceinline__ float2 unpk(unsigned long long p) {
    float2 r;
    asm("mov.b64 {%0, %1}, %2;" : "=f"(r.x), "=f"(r.y) : "l"(p));
    return r;
}
__device__ __forceinline__ unsigned long long pk(float lo, float hi) {
    unsigned long long p;
    asm("mov.b64 %0, {%1, %2};" : "=l"(p) : "f"(lo), "f"(hi));
    return p;
}

// ---------------------------------------------------------------------------
// Fused MLP, packed-f32x2 formulation (unchanged from R5 — isolate the scatter change).
__global__ __launch_bounds__(THREADS, 1)
void mlp_kernel(const float* __restrict__ x,
                const float* __restrict__ W1, const float* __restrict__ b1,
                const float* __restrict__ W2, const float* __restrict__ b2,
                float* __restrict__ out, int nNodes) {
    extern __shared__ float smem[];
    float* sA = smem;            // [128][AROW] dup'd activations (reused for hidden)
    float* sW = smem + SA_F;     // weights

    const int tid  = threadIdx.x;
    const int lane = tid & 31;
    const int warp = tid >> 5;
    const int wc   = warp * 16;            // warp's output-column base
    const int base = blockIdx.x * TM;
    const int n0   = 2 * lane;             // thread's two tile-local nodes

    // ---- load full W1 (256x128) into sW, coalesced float4 ----
    {
        const float4* src = reinterpret_cast<const float4*>(W1);
        float4* dst = reinterpret_cast<float4*>(sW);
        #pragma unroll
        for (int i = tid; i < SW_F / 4; i += THREADS) dst[i] = src[i];
    }

    unsigned long long acc[2][8];
    #pragma unroll
    for (int a = 0; a < 2; a++)
        #pragma unroll
        for (int c = 0; c < 8; c++) acc[a][c] = 0ull;

    // ---- GEMM1 in two k-phases: K 0..127 = x, K 128..255 = g_agg ----
    for (int phase = 0; phase < 2; phase++) {
        const float* src = (phase == 0) ? x : g_agg;
        if (phase == 1) __syncthreads();   // all warps done reading previous sA

        // fill sA: node n's value at k goes (duplicated) to sA[k*AROW + 2n]
        for (int i = tid; i < TM * 32; i += THREADS) {
            int n  = i & 63;               // lanes differ in n -> contiguous STS.64
            int k4 = i >> 6;
            int node = base + n;
            float4 v = {0.f, 0.f, 0.f, 0.f};
            if (node < nNodes)
                v = reinterpret_cast<const float4*>(src + (size_t)node * D)[k4];
            *(unsigned long long*)(sA + (4 * k4 + 0) * AROW + 2 * n) = pk(v.x, v.x);
            *(unsigned long long*)(sA + (4 * k4 + 1) * AROW + 2 * n) = pk(v.y, v.y);
            *(unsigned long long*)(sA + (4 * k4 + 2) * AROW + 2 * n) = pk(v.z, v.z);
            *(unsigned long long*)(sA + (4 * k4 + 3) * AROW + 2 * n) = pk(v.w, v.w);
        }
        __syncthreads();

        const float* wbase = sW + phase * 128 * 128 + wc;
        #pragma unroll 8
        for (int k = 0; k < 128; k++) {
            ulonglong2 av = *reinterpret_cast<const ulonglong2*>(sA + k * AROW + 4 * lane);
            const ulonglong2* wp = reinterpret_cast<const ulonglong2*>(wbase + k * 128);
            ulonglong2 wA = wp[0], wB = wp[1], wC = wp[2], wE = wp[3];
            fma2(acc[0][0], av.x, wA.x); fma2(acc[0][1], av.x, wA.y);
            fma2(acc[0][2], av.x, wB.x); fma2(acc[0][3], av.x, wB.y);
            fma2(acc[0][4], av.x, wC.x); fma2(acc[0][5], av.x, wC.y);
            fma2(acc[0][6], av.x, wE.x); fma2(acc[0][7], av.x, wE.y);
            fma2(acc[1][0], av.y, wA.x); fma2(acc[1][1], av.y, wA.y);
            fma2(acc[1][2], av.y, wB.x); fma2(acc[1][3], av.y, wB.y);
            fma2(acc[1][4], av.y, wC.x); fma2(acc[1][5], av.y, wC.y);
            fma2(acc[1][6], av.y, wE.x); fma2(acc[1][7], av.y, wE.y);
        }
    }

    __syncthreads();   // GEMM1 reads of sA and sW complete everywhere

    // ---- bias + relu; write hidden (duplicated) back into sA; load W2 ----
    #pragma unroll
    for (int cp = 0; cp < 8; cp++) {
        int c0 = wc + 2 * cp, c1 = c0 + 1;
        float2 h0 = unpk(acc[0][cp]);      // node n0 : cols (c0, c1)
        float2 h1 = unpk(acc[1][cp]);      // node n0+1
        float bc0 = b1[c0], bc1 = b1[c1];
        float v00 = fmaxf(h0.x + bc0, 0.f), v01 = fmaxf(h0.y + bc1, 0.f);
        float v10 = fmaxf(h1.x + bc0, 0.f), v11 = fmaxf(h1.y + bc1, 0.f);
        *(unsigned long long*)(sA + c0 * AROW + 4 * lane)     = pk(v00, v00);
        *(unsigned long long*)(sA + c0 * AROW + 4 * lane + 2) = pk(v10, v10);
        *(unsigned long long*)(sA + c1 * AROW + 4 * lane)     = pk(v01, v01);
        *(unsigned long long*)(sA + c1 * AROW + 4 * lane + 2) = pk(v11, v11);
    }
    {
        const float4* src = reinterpret_cast<const float4*>(W2);
        float4* dst = reinterpret_cast<float4*>(sW);
        #pragma unroll
        for (int i = tid; i < (128 * 128) / 4; i += THREADS) dst[i] = src[i];
    }
    __syncthreads();

    // ---- GEMM2: out = H @ W2 + b2 ----
    #pragma unroll
    for (int a = 0; a < 2; a++)
        #pragma unroll
        for (int c = 0; c < 8; c++) acc[a][c] = 0ull;

    #pragma unroll 8
    for (int k = 0; k < 128; k++) {
        ulonglong2 av = *reinterpret_cast<const ulonglong2*>(sA + k * AROW + 4 * lane);
        const ulonglong2* wp = reinterpret_cast<const ulonglong2*>(sW + k * 128 + wc);
        ulonglong2 wA = wp[0], wB = wp[1], wC = wp[2], wE = wp[3];
        fma2(acc[0][0], av.x, wA.x); fma2(acc[0][1], av.x, wA.y);
        fma2(acc[0][2], av.x, wB.x); fma2(acc[0][3], av.x, wB.y);
        fma2(acc[0][4], av.x, wC.x); fma2(acc[0][5], av.x, wC.y);
        fma2(acc[0][6], av.x, wE.x); fma2(acc[0][7], av.x, wE.y);
        fma2(acc[1][0], av.y, wA.x); fma2(acc[1][1], av.y, wA.y);
        fma2(acc[1][2], av.y, wB.x); fma2(acc[1][3], av.y, wB.y);
        fma2(acc[1][4], av.y, wC.x); fma2(acc[1][5], av.y, wC.y);
        fma2(acc[1][6], av.y, wE.x); fma2(acc[1][7], av.y, wE.y);
    }

    // ---- bias + store ----
    float o[2][16];
    #pragma unroll
    for (int cp = 0; cp < 8; cp++) {
        int c0 = wc + 2 * cp, c1 = c0 + 1;
        float2 p0 = unpk(acc[0][cp]);
        float2 p1 = unpk(acc[1][cp]);
        float bc0 = b2[c0], bc1 = b2[c1];
        o[0][2 * cp]     = p0.x + bc0;
        o[0][2 * cp + 1] = p0.y + bc1;
        o[1][2 * cp]     = p1.x + bc0;
        o[1][2 * cp + 1] = p1.y + bc1;
    }
    #pragma unroll
    for (int q = 0; q < 2; q++) {
        int node = base + n0 + q;
        if (node < nNodes) {
            float* dst = out + (size_t)node * D + wc;
            #pragma unroll
            for (int t = 0; t < 4; t++) {
                float4 v = make_float4(o[q][4 * t], o[q][4 * t + 1],
                                       o[q][4 * t + 2], o[q][4 * t + 3]);
                *reinterpret_cast<float4*>(dst + 4 * t) = v;
            }
        }
    }
}

// ---------------------------------------------------------------------------
extern "C" void kernel_launch(void* const* d_in, const int* in_sizes, int n_in,
                              void* d_out, int out_size) {
    const float* x         = (const float*)d_in[0];
    const float* edge_attr = (const float*)d_in[1];
    const int*   recv      = (const int*)d_in[2];
    const float* W1        = (const float*)d_in[3];
    const float* b1        = (const float*)d_in[4];
    const float* W2        = (const float*)d_in[5];
    const float* b2        = (const float*)d_in[6];
    float* out = (float*)d_out;

    int nNodes = in_sizes[0] / D;
    int E      = in_sizes[2];

    cudaFuncSetAttribute(mlp_kernel, cudaFuncAttributeMaxDynamicSharedMemorySize,
                         SMEM_BYTES);

    // 1) zero aggregate
    int n4 = nNodes * D / 4;
    zero_agg_kernel<<<(n4 + 255) / 256, 256>>>(n4);

    // 2) scatter-add edge features via TMA bulk-reduce
    int totalWarps = SC_CTAS * SC_WARPS;
    scatter_tma_kernel<<<SC_CTAS, THREADS>>>(edge_attr, recv, E, totalWarps);

    // 3) fused MLP (packed f32x2)
    int tiles = (nNodes + TM - 1) / TM;
    mlp_kernel<<<tiles, THREADS, SMEM_BYTES>>>(x, W1, b1, W2, b2, out, nNodes);
}